// round 2
// baseline (speedup 1.0000x reference)
#include <cuda_runtime.h>
#include <cstdint>

#define DEV_INLINE __device__ __forceinline__

// ------------- device-global scratch (allocation-free per harness rules) ------
static __device__ float g_G[2ULL * 512 * 64 * 2048];   // gate preactivations, per dir [T][B][4H]
static __device__ float g_h1[512 * 64 * 1024];         // layer-0 output [T][B][2H] (tf32-rounded)
static __device__ float g_h2[512 * 64 * 1024];         // layer-1 output
static __device__ float g_xr[64 * 512 * 168];          // tf32-rounded x
static __device__ float g_w0r[2 * 2048 * 168];
static __device__ float g_w1r[2 * 2048 * 1024];
static __device__ float g_wor[168 * 1024];
static __device__ float g_hbuf[2][2][64][512];         // [dir][parity][b][k] recurrent h
static __device__ int   g_bar[4][32];                  // barrier counters [layer*2+dir]

// ------------- helpers -------------
DEV_INLINE unsigned sptr(const void* p) { return (unsigned)__cvta_generic_to_shared(p); }

DEV_INLINE void cp16(void* d, const void* s, int bytes) {
    asm volatile("cp.async.cg.shared.global [%0],[%1],16,%2;\n"
                 :: "r"(sptr(d)), "l"(s), "r"(bytes));
}
DEV_INLINE void cp_commit() { asm volatile("cp.async.commit_group;\n"); }
DEV_INLINE void cp_wait0()  { asm volatile("cp.async.wait_group 0;\n"); }
DEV_INLINE void cp_wait1()  { asm volatile("cp.async.wait_group 1;\n"); }

DEV_INLINE float tf32r(float x) {
    unsigned r;
    asm("cvt.rna.tf32.f32 %0, %1;" : "=r"(r) : "f"(x));
    return __uint_as_float(r);
}

DEV_INLINE void mma8(float c[4], const unsigned a[4], const unsigned b[2]) {
    asm volatile("mma.sync.aligned.m16n8k8.row.col.f32.tf32.tf32.f32 "
                 "{%0,%1,%2,%3},{%4,%5,%6,%7},{%8,%9},{%0,%1,%2,%3};"
                 : "+f"(c[0]), "+f"(c[1]), "+f"(c[2]), "+f"(c[3])
                 : "r"(a[0]), "r"(a[1]), "r"(a[2]), "r"(a[3]),
                   "r"(b[0]), "r"(b[1]));
}

DEV_INLINE int ld_acq(const int* p) {
    int v;
    asm volatile("ld.acquire.gpu.global.b32 %0,[%1];" : "=r"(v) : "l"(p) : "memory");
    return v;
}

DEV_INLINE float sigm(float x)   { return 1.0f / (1.0f + __expf(-x)); }
DEV_INLINE float tanh_f(float x) { float e = __expf(2.0f * x); return 1.0f - 2.0f / (e + 1.0f); }

// ------------- tiny kernels -------------
__global__ void round_k(const float* __restrict__ in, float* __restrict__ out, int n) {
    for (int i = blockIdx.x * blockDim.x + threadIdx.x; i < n; i += gridDim.x * blockDim.x)
        out[i] = tf32r(in[i]);
}

__global__ void reset_k() {
    int gt = blockIdx.x * 256 + threadIdx.x;
    if (gt < 128) ((int*)g_bar)[gt] = 0;
    float* hb = &g_hbuf[0][0][0][0];
    for (int i = gt; i < 2 * 2 * 64 * 512; i += 64 * 256) hb[i] = 0.0f;
}

// ------------- generic tf32 GEMM: C = A[m,:]·W[n,:] + bias[n] -------------
// tile 128(M) x 64(N), k-tile 16, 256 threads (warps 4m x 2n, each m32 x n32)
// out offset = (m/DIV)*S1 + (m%DIV)*S2 + n
__global__ void __launch_bounds__(256, 2)
gemm_k(const float* __restrict__ A, const float* __restrict__ W,
       const float* __restrict__ bias, float* __restrict__ C,
       int M, int N, int K, int DIV, long long S1, long long S2) {
    __shared__ float As[2][128 * 20];
    __shared__ float Bs[2][64 * 20];

    int tid = threadIdx.x, lane = tid & 31, wid = tid >> 5;
    int wm = wid & 3, wn = wid >> 2;
    int mbase = blockIdx.y * 128, nbase = blockIdx.x * 64;
    int KT = (K + 15) >> 4;

    float acc[2][4][4];
#pragma unroll
    for (int mt = 0; mt < 2; mt++)
#pragma unroll
        for (int nt = 0; nt < 4; nt++)
#pragma unroll
            for (int e = 0; e < 4; e++) acc[mt][nt][e] = 0.0f;

    auto load_stage = [&](int kt, int s) {
        int k0 = kt * 16;
#pragma unroll
        for (int i = 0; i < 2; i++) {
            int ch = i * 256 + tid;
            int row = ch >> 2, seg = ch & 3;
            int k = k0 + seg * 4;
            int el = K - k; if (el > 4) el = 4; if (el < 0) el = 0;
            int bytes = el * 4;
            const float* src = A + (size_t)(mbase + row) * K + (bytes ? k : 0);
            cp16(&As[s][row * 20 + seg * 4], src, bytes);
        }
        {
            int row = tid >> 2, seg = tid & 3;
            int k = k0 + seg * 4;
            int n = nbase + row;
            int el = K - k; if (el > 4) el = 4; if (el < 0) el = 0;
            int bytes = el * 4;
            if (n >= N) bytes = 0;
            const float* src = (bytes ? (W + (size_t)n * K + k) : W);
            cp16(&Bs[s][row * 20 + seg * 4], src, bytes);
        }
        cp_commit();
    };

    load_stage(0, 0);

    for (int kt = 0; kt < KT; kt++) {
        cp_wait0();
        __syncthreads();
        if (kt + 1 < KT) load_stage(kt + 1, (kt + 1) & 1);
        const float* as = As[kt & 1];
        const float* bs = Bs[kt & 1];
#pragma unroll
        for (int k8 = 0; k8 < 2; k8++) {
            int kk = k8 * 8 + (lane & 3);
            unsigned a[2][4], b[4][2];
#pragma unroll
            for (int mt = 0; mt < 2; mt++) {
                int r0 = wm * 32 + mt * 16 + (lane >> 2);
                a[mt][0] = __float_as_uint(as[r0 * 20 + kk]);
                a[mt][1] = __float_as_uint(as[(r0 + 8) * 20 + kk]);
                a[mt][2] = __float_as_uint(as[r0 * 20 + kk + 4]);
                a[mt][3] = __float_as_uint(as[(r0 + 8) * 20 + kk + 4]);
            }
#pragma unroll
            for (int nt = 0; nt < 4; nt++) {
                int c0 = wn * 32 + nt * 8 + (lane >> 2);
                b[nt][0] = __float_as_uint(bs[c0 * 20 + kk]);
                b[nt][1] = __float_as_uint(bs[c0 * 20 + kk + 4]);
            }
#pragma unroll
            for (int mt = 0; mt < 2; mt++)
#pragma unroll
                for (int nt = 0; nt < 4; nt++)
                    mma8(acc[mt][nt], a[mt], b[nt]);
        }
        __syncthreads();
    }

#pragma unroll
    for (int mt = 0; mt < 2; mt++) {
#pragma unroll
        for (int nt = 0; nt < 4; nt++) {
            int m0 = mbase + wm * 32 + mt * 16 + (lane >> 2);
            int n0 = nbase + wn * 32 + nt * 8 + 2 * (lane & 3);
            if (n0 < N) {
                float bv0 = bias[n0], bv1 = bias[n0 + 1];
                long long o0 = (long long)(m0 / DIV) * S1 + (long long)(m0 % DIV) * S2 + n0;
                int m1 = m0 + 8;
                long long o1 = (long long)(m1 / DIV) * S1 + (long long)(m1 % DIV) * S2 + n0;
                *(float2*)(C + o0) = make_float2(acc[mt][nt][0] + bv0, acc[mt][nt][1] + bv1);
                *(float2*)(C + o1) = make_float2(acc[mt][nt][2] + bv0, acc[mt][nt][3] + bv1);
            }
        }
    }
}

// ------------- persistent bidirectional LSTM recurrence -------------
// grid 64: dir = bx/32, cta = bx%32 owns hidden units [cta*16, cta*16+16)
// 128 threads (4 warps: 2m x 2n, warp tile m32 x n32). m = batch, n = 64 gate rows
// SMEM row n of Whh slice: jloc = n>>2, gate g = n&3, global row = g*512 + jbase + jloc
__global__ void __launch_bounds__(128, 1)
lstm_k(const float* __restrict__ Whh, const float* __restrict__ G,
       float* __restrict__ hout, int layer) {
    extern __shared__ float sm[];
    float* whh = sm;                       // 64 x 516
    float* hs  = sm + 64 * 516;            // 2 x (64 x 68)
    float* Gs  = hs + 2 * 64 * 68;         // 64 x 64
    float* dmp = Gs + 64 * 64;             // 64 x 68

    const int tid = threadIdx.x;
    const int lane = tid & 31, wid = tid >> 5;
    const int wm = wid & 1, wn = wid >> 1;
    const int d = blockIdx.x >> 5;
    const int jbase = (blockIdx.x & 31) * 16;
    int* bar = &g_bar[layer * 2 + d][0];

    const float* Wd = Whh + (size_t)d * 2048 * 512;
    for (int idx = tid; idx < 64 * 512; idx += 128) {
        int n = idx >> 9, k = idx & 511;
        int grow = (n & 3) * 512 + jbase + (n >> 2);
        whh[n * 516 + k] = tf32r(Wd[(size_t)grow * 512 + k]);
    }
    __syncthreads();

    const float* Gbase = G + (size_t)d * 512 * 64 * 2048;
    float cst[8];
#pragma unroll
    for (int i = 0; i < 8; i++) cst[i] = 0.0f;
    const int b_ep = tid >> 1;
    const int half = tid & 1;

    for (int t = 0; t < 512; t++) {
        if (tid == 0 && t > 0) {
            while (ld_acq(bar) < 32 * t) __nanosleep(32);
        }
        __syncthreads();

        int tt = d ? (511 - t) : t;
        const float* Gp = Gbase + (size_t)tt * 64 * 2048;
#pragma unroll
        for (int i = 0; i < 8; i++) {
            int s = tid * 8 + i;                    // 0..1023
            int b = s >> 4, g = (s >> 2) & 3, part = s & 3;
            cp16(Gs + b * 64 + g * 16 + part * 4,
                 Gp + (size_t)b * 2048 + g * 512 + jbase + part * 4, 16);
        }
        cp_commit();

        const float* hsrc = &g_hbuf[d][(t + 1) & 1][0][0];
#pragma unroll
        for (int i = 0; i < 8; i++) {
            int s = tid * 8 + i;
            int b = s >> 4, kp = (s & 15) * 4;
            cp16(hs + b * 68 + kp, hsrc + b * 512 + kp, 16);
        }
        cp_commit();

        float acc[2][4][4];
#pragma unroll
        for (int mt = 0; mt < 2; mt++)
#pragma unroll
            for (int nt = 0; nt < 4; nt++)
#pragma unroll
                for (int e = 0; e < 4; e++) acc[mt][nt][e] = 0.0f;

        for (int c = 0; c < 8; c++) {
            if (c < 7) {
                const float* src = hsrc + (c + 1) * 64;
                float* dst = hs + ((c + 1) & 1) * (64 * 68);
#pragma unroll
                for (int i = 0; i < 8; i++) {
                    int s = tid * 8 + i;
                    int b = s >> 4, kp = (s & 15) * 4;
                    cp16(dst + b * 68 + kp, src + b * 512 + kp, 16);
                }
                cp_commit();
                cp_wait1();
            } else {
                cp_wait0();
            }
            __syncthreads();           // chunk c visible to all
            const float* hc = hs + (c & 1) * (64 * 68);
#pragma unroll
            for (int k8 = 0; k8 < 8; k8++) {
                int kk = k8 * 8 + (lane & 3);
                int ra = wm * 32 + (lane >> 2);
                unsigned a[2][4], bb[4][2];
#pragma unroll
                for (int mt = 0; mt < 2; mt++) {
                    int r = ra + mt * 16;
                    a[mt][0] = __float_as_uint(hc[r * 68 + kk]);
                    a[mt][1] = __float_as_uint(hc[(r + 8) * 68 + kk]);
                    a[mt][2] = __float_as_uint(hc[r * 68 + kk + 4]);
                    a[mt][3] = __float_as_uint(hc[(r + 8) * 68 + kk + 4]);
                }
                int kw = c * 64 + kk;
#pragma unroll
                for (int nt = 0; nt < 4; nt++) {
                    int nn = wn * 32 + nt * 8 + (lane >> 2);
                    bb[nt][0] = __float_as_uint(whh[nn * 516 + kw]);
                    bb[nt][1] = __float_as_uint(whh[nn * 516 + kw + 4]);
                }
#pragma unroll
                for (int mt = 0; mt < 2; mt++)
#pragma unroll
                    for (int nt = 0; nt < 4; nt++)
                        mma8(acc[mt][nt], a[mt], bb[nt]);
            }
            __syncthreads();           // all reads of this buffer done
        }

        // dump gates to SMEM
#pragma unroll
        for (int mt = 0; mt < 2; mt++) {
#pragma unroll
            for (int nt = 0; nt < 4; nt++) {
                int m0 = wm * 32 + mt * 16 + (lane >> 2);
                int n0 = wn * 32 + nt * 8 + 2 * (lane & 3);
                dmp[m0 * 68 + n0]       = acc[mt][nt][0];
                dmp[m0 * 68 + n0 + 1]   = acc[mt][nt][1];
                dmp[(m0 + 8) * 68 + n0]     = acc[mt][nt][2];
                dmp[(m0 + 8) * 68 + n0 + 1] = acc[mt][nt][3];
            }
        }
        __syncthreads();

        // epilogue: thread handles (b_ep, jloc = half*8 + 0..7)
        float hr[8];
#pragma unroll
        for (int i = 0; i < 8; i++) {
            int jloc = half * 8 + i;
            float gi = dmp[b_ep * 68 + jloc * 4 + 0] + Gs[b_ep * 64 + jloc];
            float gf = dmp[b_ep * 68 + jloc * 4 + 1] + Gs[b_ep * 64 + 16 + jloc];
            float gg = dmp[b_ep * 68 + jloc * 4 + 2] + Gs[b_ep * 64 + 32 + jloc];
            float go = dmp[b_ep * 68 + jloc * 4 + 3] + Gs[b_ep * 64 + 48 + jloc];
            float cv = sigm(gf) * cst[i] + sigm(gi) * tanh_f(gg);
            cst[i] = cv;
            hr[i] = tf32r(sigm(go) * tanh_f(cv));
        }
        float* hb = &g_hbuf[d][t & 1][b_ep][jbase + half * 8];
        *(float4*)hb       = make_float4(hr[0], hr[1], hr[2], hr[3]);
        *(float4*)(hb + 4) = make_float4(hr[4], hr[5], hr[6], hr[7]);
        float* ho = hout + ((size_t)tt * 64 + b_ep) * 1024 + d * 512 + jbase + half * 8;
        *(float4*)ho       = make_float4(hr[0], hr[1], hr[2], hr[3]);
        *(float4*)(ho + 4) = make_float4(hr[4], hr[5], hr[6], hr[7]);
        __syncthreads();
        if (tid == 0 && t < 511) { __threadfence(); atomicAdd(bar, 1); }
    }
}

// ------------- host launcher -------------
extern "C" void kernel_launch(void* const* d_in, const int* in_sizes, int n_in,
                              void* d_out, int out_size) {
    (void)in_sizes; (void)n_in; (void)out_size;
    const float* x    = (const float*)d_in[0];
    const float* Wih0 = (const float*)d_in[1];
    const float* Whh0 = (const float*)d_in[2];
    const float* b0   = (const float*)d_in[3];
    const float* Wih1 = (const float*)d_in[4];
    const float* Whh1 = (const float*)d_in[5];
    const float* b1   = (const float*)d_in[6];
    const float* Wout = (const float*)d_in[7];
    const float* bout = (const float*)d_in[8];
    float* out = (float*)d_out;

    const int SMEM = (64 * 516 + 2 * 64 * 68 + 64 * 64 + 64 * 68) * 4;  // 200704
    cudaFuncSetAttribute(lstm_k, cudaFuncAttributeMaxDynamicSharedMemorySize, SMEM);

    float *xr, *w0r, *w1r, *wor, *G, *h1, *h2;
    cudaGetSymbolAddress((void**)&xr,  g_xr);
    cudaGetSymbolAddress((void**)&w0r, g_w0r);
    cudaGetSymbolAddress((void**)&w1r, g_w1r);
    cudaGetSymbolAddress((void**)&wor, g_wor);
    cudaGetSymbolAddress((void**)&G,   g_G);
    cudaGetSymbolAddress((void**)&h1,  g_h1);
    cudaGetSymbolAddress((void**)&h2,  g_h2);

    const long long GSZ = 512LL * 64 * 2048;

    round_k<<<1024, 256>>>(x,    xr,  64 * 512 * 168);
    round_k<<<256,  256>>>(Wih0, w0r, 2 * 2048 * 168);
    round_k<<<1024, 256>>>(Wih1, w1r, 2 * 2048 * 1024);
    round_k<<<128,  256>>>(Wout, wor, 168 * 1024);

    dim3 gg(32, 256);
    for (int d = 0; d < 2; d++)
        gemm_k<<<gg, 256>>>(xr, w0r + (size_t)d * 2048 * 168, b0 + d * 2048,
                            G + d * GSZ, 32768, 2048, 168, 512, 2048LL, 131072LL);
    reset_k<<<64, 256>>>();
    lstm_k<<<64, 128, SMEM>>>(Whh0, G, h1, 0);

    for (int d = 0; d < 2; d++)
        gemm_k<<<gg, 256>>>(h1, w1r + (size_t)d * 2048 * 1024, b1 + d * 2048,
                            G + d * GSZ, 32768, 2048, 1024, 64, 131072LL, 2048LL);
    reset_k<<<64, 256>>>();
    lstm_k<<<64, 128, SMEM>>>(Whh1, G, h2, 1);

    dim3 go(3, 256);
    gemm_k<<<go, 256>>>(h2, wor, bout, out, 32768, 168, 1024, 64, 168LL, 86016LL);
}